// round 1
// baseline (speedup 1.0000x reference)
#include <cuda_runtime.h>
#include <math.h>

// Problem constants (fixed by the reference: B=2048, A=32, D=128, H=256)
#define NB    2048
#define NA    32
#define NROWS (NB * NA)   // 65536
#define DIN   128
#define HD    256
#define H3    768

// ---------------------------------------------------------------------------
// Scratch (no allocations allowed -> __device__ globals).
//   g_e  : encoder output e, later reused as comm tensor c
//   g_h  : h after fobs GEMM
//   g_h1 : h after GRU step k=0
//   g_gh : gh = h @ W_hh^T + b_hh (reused for k=1's gh)
//   g_gi : gi = c @ W_ih^T + b_ih (k=1 only; k=0's gi is just b_ih)
// ---------------------------------------------------------------------------
__device__ float g_e [(size_t)NROWS * HD];
__device__ float g_h [(size_t)NROWS * HD];
__device__ float g_h1[(size_t)NROWS * HD];
__device__ float g_gh[(size_t)NROWS * H3];
__device__ float g_gi[(size_t)NROWS * H3];

__device__ __forceinline__ float sigmoidf_(float x) {
    return 1.0f / (1.0f + expf(-x));
}

// ---------------------------------------------------------------------------
// Tiled fp32 GEMM:  C[N,M] = A[N,K] @ W[M,K]^T + bias[M]   (optionally ReLU)
// BM=BN=128, BK=8, 256 threads, 8x8 accumulator per thread.
// Requires: N % 128 == 0, M % 128 == 0, K % 8 == 0  (true for all our shapes)
// ---------------------------------------------------------------------------
template <bool RELU>
__global__ __launch_bounds__(256, 2)
void sgemm_bias(const float* __restrict__ A, const float* __restrict__ W,
                const float* __restrict__ bias, float* __restrict__ C,
                int K, int M)
{
    constexpr int BM = 128, BN = 128, BK = 8;
    __shared__ float As[BK][BM];
    __shared__ float Bs[BK][BN];

    const int tid  = threadIdx.x;
    const int row0 = blockIdx.y * BM;
    const int col0 = blockIdx.x * BN;
    const int tx = tid & 15;   // 0..15 -> output col sub-tile
    const int ty = tid >> 4;   // 0..15 -> output row sub-tile

    // Tile loading: each thread loads one float4 of A and one of W per k-step.
    const int lr = tid >> 1;        // 0..127 (tile row)
    const int lc = (tid & 1) * 4;   // 0 or 4 (k offset)

    const float* Ap = A + (size_t)(row0 + lr) * K + lc;
    const float* Wp = W + (size_t)(col0 + lr) * K + lc;

    float acc[8][8];
#pragma unroll
    for (int i = 0; i < 8; i++)
#pragma unroll
        for (int j = 0; j < 8; j++) acc[i][j] = 0.f;

    for (int k0 = 0; k0 < K; k0 += BK) {
        float4 av = *reinterpret_cast<const float4*>(Ap + k0);
        float4 wv = *reinterpret_cast<const float4*>(Wp + k0);
        As[lc + 0][lr] = av.x; As[lc + 1][lr] = av.y;
        As[lc + 2][lr] = av.z; As[lc + 3][lr] = av.w;
        Bs[lc + 0][lr] = wv.x; Bs[lc + 1][lr] = wv.y;
        Bs[lc + 2][lr] = wv.z; Bs[lc + 3][lr] = wv.w;
        __syncthreads();

#pragma unroll
        for (int kk = 0; kk < BK; kk++) {
            float a[8], b[8];
            *reinterpret_cast<float4*>(a)     = *reinterpret_cast<const float4*>(&As[kk][ty * 8]);
            *reinterpret_cast<float4*>(a + 4) = *reinterpret_cast<const float4*>(&As[kk][ty * 8 + 4]);
            *reinterpret_cast<float4*>(b)     = *reinterpret_cast<const float4*>(&Bs[kk][tx * 8]);
            *reinterpret_cast<float4*>(b + 4) = *reinterpret_cast<const float4*>(&Bs[kk][tx * 8 + 4]);
#pragma unroll
            for (int i = 0; i < 8; i++)
#pragma unroll
                for (int j = 0; j < 8; j++)
                    acc[i][j] = fmaf(a[i], b[j], acc[i][j]);
        }
        __syncthreads();
    }

#pragma unroll
    for (int i = 0; i < 8; i++) {
        const int row = row0 + ty * 8 + i;
#pragma unroll
        for (int j = 0; j < 8; j += 4) {
            const int col = col0 + tx * 8 + j;
            float4 v;
            v.x = acc[i][j + 0] + bias[col + 0];
            v.y = acc[i][j + 1] + bias[col + 1];
            v.z = acc[i][j + 2] + bias[col + 2];
            v.w = acc[i][j + 3] + bias[col + 3];
            if (RELU) {
                v.x = fmaxf(v.x, 0.f); v.y = fmaxf(v.y, 0.f);
                v.z = fmaxf(v.z, 0.f); v.w = fmaxf(v.w, 0.f);
            }
            *reinterpret_cast<float4*>(&C[(size_t)row * M + col]) = v;
        }
    }
}

// ---------------------------------------------------------------------------
// GRU gates, step k=0 (x == 0, so gi == b_ih broadcast).
//   gh already includes b_hh (GEMM bias). Writes h1.
// ---------------------------------------------------------------------------
__global__ void gates0_kernel(const float* __restrict__ gh,
                              const float* __restrict__ b_ih,
                              const float* __restrict__ h,
                              float* __restrict__ h1)
{
    const int idx = blockIdx.x * blockDim.x + threadIdx.x;  // over NROWS*HD
    const int i = idx >> 8;        // row
    const int j = idx & 255;       // hidden index
    const float* ghr = gh + (size_t)i * H3;
    const float r = sigmoidf_(b_ih[j]       + ghr[j]);
    const float z = sigmoidf_(b_ih[HD + j]  + ghr[HD + j]);
    const float n = tanhf   (b_ih[2*HD + j] + r * ghr[2*HD + j]);
    h1[idx] = (1.f - z) * n + z * h[idx];
}

// ---------------------------------------------------------------------------
// Comm tensor: c[b,a,j] = (sum_a' h1[b,a',j] - h1[b,a,j]) / NA
// One block per batch, one thread per hidden column.
// ---------------------------------------------------------------------------
__global__ void comm_kernel(const float* __restrict__ h1, float* __restrict__ c)
{
    const int b = blockIdx.x;
    const int j = threadIdx.x;
    const float* base = h1 + (size_t)b * NA * HD + j;
    float v[NA];
    float s = 0.f;
#pragma unroll
    for (int a = 0; a < NA; a++) { v[a] = base[a * HD]; s += v[a]; }
    float* cb = c + (size_t)b * NA * HD + j;
    const float inv = 1.f / (float)NA;
#pragma unroll
    for (int a = 0; a < NA; a++) cb[a * HD] = (s - v[a]) * inv;
}

// ---------------------------------------------------------------------------
// GRU gates step k=1 fused with the H->1 decoder (block-wide dot product).
// One block (256 threads) per row. gi includes b_ih, gh includes b_hh.
// ---------------------------------------------------------------------------
__global__ void gates1_dec_kernel(const float* __restrict__ gi,
                                  const float* __restrict__ gh,
                                  const float* __restrict__ h1,
                                  const float* __restrict__ dec_W,
                                  const float* __restrict__ dec_b,
                                  float* __restrict__ out)
{
    const int i = blockIdx.x;
    const int j = threadIdx.x;
    const float* gir = gi + (size_t)i * H3;
    const float* ghr = gh + (size_t)i * H3;
    const float r  = sigmoidf_(gir[j]        + ghr[j]);
    const float z  = sigmoidf_(gir[HD + j]   + ghr[HD + j]);
    const float n  = tanhf   (gir[2*HD + j]  + r * ghr[2*HD + j]);
    const float h2 = (1.f - z) * n + z * h1[(size_t)i * HD + j];

    float p = h2 * dec_W[j];

    // block reduction over 256 threads
    __shared__ float red[8];
#pragma unroll
    for (int o = 16; o > 0; o >>= 1) p += __shfl_down_sync(0xffffffffu, p, o);
    if ((j & 31) == 0) red[j >> 5] = p;
    __syncthreads();
    if (j < 8) {
        float v = red[j];
#pragma unroll
        for (int o = 4; o > 0; o >>= 1) v += __shfl_down_sync(0xffu, v, o);
        if (j == 0) out[i] = v + dec_b[0];
    }
}

// ---------------------------------------------------------------------------
// Launch: 8 kernels, all graph-capturable (no sync, no alloc).
// Input order (metadata): obs, act, enc_W, enc_b, fobs_W, fobs_b,
//                         W_ih, b_ih, W_hh, b_hh, dec_W, dec_b
// ---------------------------------------------------------------------------
extern "C" void kernel_launch(void* const* d_in, const int* in_sizes, int n_in,
                              void* d_out, int out_size)
{
    const float* obs    = (const float*)d_in[0];
    const float* enc_W  = (const float*)d_in[2];
    const float* enc_b  = (const float*)d_in[3];
    const float* fobs_W = (const float*)d_in[4];
    const float* fobs_b = (const float*)d_in[5];
    const float* W_ih   = (const float*)d_in[6];
    const float* b_ih   = (const float*)d_in[7];
    const float* W_hh   = (const float*)d_in[8];
    const float* b_hh   = (const float*)d_in[9];
    const float* dec_W  = (const float*)d_in[10];
    const float* dec_b  = (const float*)d_in[11];
    float* out = (float*)d_out;

    float *e, *h, *h1, *gh, *gi;
    cudaGetSymbolAddress((void**)&e,  g_e);
    cudaGetSymbolAddress((void**)&h,  g_h);
    cudaGetSymbolAddress((void**)&h1, g_h1);
    cudaGetSymbolAddress((void**)&gh, g_gh);
    cudaGetSymbolAddress((void**)&gi, g_gi);

    const dim3 blk(256);
    const int rowBlocks = NROWS / 128;  // 512

    // 1) e = relu(obs @ enc_W^T + enc_b)           [N,128]x[128->256]
    sgemm_bias<true ><<<dim3(HD / 128, rowBlocks), blk>>>(obs, enc_W, enc_b, e, DIN, HD);
    // 2) h = e @ fobs_W^T + fobs_b                 [N,256]x[256->256]
    sgemm_bias<false><<<dim3(HD / 128, rowBlocks), blk>>>(e, fobs_W, fobs_b, h, HD, HD);
    // 3) gh = h @ W_hh^T + b_hh                    [N,256]x[256->768]
    sgemm_bias<false><<<dim3(H3 / 128, rowBlocks), blk>>>(h, W_hh, b_hh, gh, HD, H3);
    // 4) GRU k=0 gates -> h1   (gi == b_ih since x == 0)
    gates0_kernel<<<(NROWS * HD) / 256, 256>>>(gh, b_ih, h, h1);
    // 5) c = masked mean over other agents  (reuse e as c)
    comm_kernel<<<NB, HD>>>(h1, e);
    // 6) gi = c @ W_ih^T + b_ih
    sgemm_bias<false><<<dim3(H3 / 128, rowBlocks), blk>>>(e, W_ih, b_ih, gi, HD, H3);
    // 7) gh = h1 @ W_hh^T + b_hh   (reuse gh buffer)
    sgemm_bias<false><<<dim3(H3 / 128, rowBlocks), blk>>>(h1, W_hh, b_hh, gh, HD, H3);
    // 8) GRU k=1 gates + decoder -> out [N,1]
    gates1_dec_kernel<<<NROWS, HD>>>(gi, gh, h1, dec_W, dec_b, out);
}

// round 3
// speedup vs baseline: 1.4872x; 1.4872x over previous
#include <cuda_runtime.h>
#include <cuda_bf16.h>
#include <math.h>
#include <stdint.h>

// Problem constants (B=2048, A=32, D=128, H=256)
#define NB    2048
#define NA    32
#define NROWS (NB * NA)   // 65536
#define DIN   128
#define HD    256
#define H3    768

// ---------------------------------------------------------------------------
// Scratch (__device__ globals; no allocations allowed)
// ---------------------------------------------------------------------------
__device__ float g_e [(size_t)NROWS * HD];   // encoder out, reused as comm c
__device__ float g_h [(size_t)NROWS * HD];
__device__ float g_h1[(size_t)NROWS * HD];
__device__ float g_gh[(size_t)NROWS * H3];
__device__ float g_gi[(size_t)NROWS * H3];

__device__ __forceinline__ float sigmoidf_(float x) { return 1.0f / (1.0f + expf(-x)); }

__device__ __forceinline__ uint32_t smem_to_u32(const void* p) {
    uint32_t a;
    asm("{ .reg .u64 t; cvta.to.shared.u64 t, %1; cvt.u32.u64 %0, t; }" : "=r"(a) : "l"(p));
    return a;
}

#define SMEM_SWIZZLE_128B(off) ((off) ^ (((off) >> 3) & 0x70))

// ---------------------------------------------------------------------------
// Warp-level bf16 MMA building blocks (baseline sm_80+ ISA; no tcgen05)
// ---------------------------------------------------------------------------
__device__ __forceinline__ void mma_bf16(float* c, uint32_t a0, uint32_t a1, uint32_t a2,
                                         uint32_t a3, uint32_t b0, uint32_t b1) {
    asm volatile(
        "mma.sync.aligned.m16n8k16.row.col.f32.bf16.bf16.f32 "
        "{%0,%1,%2,%3}, {%4,%5,%6,%7}, {%8,%9}, {%0,%1,%2,%3};"
        : "+f"(c[0]), "+f"(c[1]), "+f"(c[2]), "+f"(c[3])
        : "r"(a0), "r"(a1), "r"(a2), "r"(a3), "r"(b0), "r"(b1));
}
__device__ __forceinline__ void ldm_x4(uint32_t* r, uint32_t addr) {
    asm volatile("ldmatrix.sync.aligned.m8n8.x4.shared.b16 {%0,%1,%2,%3}, [%4];"
                 : "=r"(r[0]), "=r"(r[1]), "=r"(r[2]), "=r"(r[3]) : "r"(addr));
}
__device__ __forceinline__ void ldm_x2(uint32_t* r, uint32_t addr) {
    asm volatile("ldmatrix.sync.aligned.m8n8.x2.shared.b16 {%0,%1}, [%2];"
                 : "=r"(r[0]), "=r"(r[1]) : "r"(addr));
}

// Split 8 fp32 into bf16 hi + bf16 lo (residual), store 16B each, swizzled.
__device__ __forceinline__ void split8_store(const float4 v0, const float4 v1,
                                             char* smem, uint32_t hi_off, uint32_t lo_off) {
    float x[8] = {v0.x, v0.y, v0.z, v0.w, v1.x, v1.y, v1.z, v1.w};
    uint32_t hw[4], lw[4];
#pragma unroll
    for (int p = 0; p < 4; p++) {
        __nv_bfloat16 h0 = __float2bfloat16_rn(x[2*p]);
        __nv_bfloat16 h1 = __float2bfloat16_rn(x[2*p+1]);
        float r0 = x[2*p]   - __bfloat162float(h0);
        float r1 = x[2*p+1] - __bfloat162float(h1);
        __nv_bfloat16 l0 = __float2bfloat16_rn(r0);
        __nv_bfloat16 l1 = __float2bfloat16_rn(r1);
        hw[p] = (uint32_t)__bfloat16_as_ushort(h0) | ((uint32_t)__bfloat16_as_ushort(h1) << 16);
        lw[p] = (uint32_t)__bfloat16_as_ushort(l0) | ((uint32_t)__bfloat16_as_ushort(l1) << 16);
    }
    *reinterpret_cast<uint4*>(smem + hi_off) = make_uint4(hw[0], hw[1], hw[2], hw[3]);
    *reinterpret_cast<uint4*>(smem + lo_off) = make_uint4(lw[0], lw[1], lw[2], lw[3]);
}

// ---------------------------------------------------------------------------
// bf16-split GEMM via mma.sync:  C[N,M] = A[N,K] @ W[M,K]^T + bias (opt ReLU)
// CTA tile 128x128, KC=64. 8 warps (2m x 4n), warp tile 64x32.
// Requires N%128==0, M%128==0, K%64==0.
// ---------------------------------------------------------------------------
#define SM_A_HI 0
#define SM_A_LO 16384
#define SM_W_HI 32768
#define SM_W_LO 49152
#define SM_TOTAL 65536

template <bool RELU>
__global__ __launch_bounds__(256)
void mma_gemm(const float* __restrict__ A, const float* __restrict__ W,
              const float* __restrict__ bias, float* __restrict__ C,
              int K, int M)
{
    extern __shared__ char smem[];
    const uint32_t sb = smem_to_u32(smem);
    const int tid  = threadIdx.x;
    const int wid  = tid >> 5;
    const int lane = tid & 31;
    const int row0 = blockIdx.y * 128;
    const int col0 = blockIdx.x * 128;

    const int wm0 = (wid >> 2) * 64;   // warp m offset: 0 or 64
    const int wn0 = (wid & 3) * 32;    // warp n offset: 0,32,64,96

    // ldmatrix per-lane address components
    const int a_row = wm0 + (lane & 15);          // + fm*16
    const int a_kb  = ((lane >> 4) & 1) * 16;     // k-half byte offset
    const int b_row = wn0 + (lane & 7);           // + fn*8
    const int b_kb  = ((lane >> 3) & 1) * 16;

    float acc[4][4][4];
#pragma unroll
    for (int i = 0; i < 4; i++)
#pragma unroll
        for (int j = 0; j < 4; j++)
#pragma unroll
            for (int q = 0; q < 4; q++) acc[i][j][q] = 0.f;

    const int nchunks = K >> 6;
    for (int ch = 0; ch < nchunks; ch++) {
        if (ch > 0) __syncthreads();

        // load + split A tile: 128 x 64 floats
#pragma unroll
        for (int it = 0; it < 4; it++) {
            int g  = tid + it * 256;
            int r  = g >> 3;
            int k0 = (g & 7) * 8;
            const float* p = A + (size_t)(row0 + r) * K + ch * 64 + k0;
            float4 v0 = *reinterpret_cast<const float4*>(p);
            float4 v1 = *reinterpret_cast<const float4*>(p + 4);
            uint32_t off = SMEM_SWIZZLE_128B((uint32_t)(r * 128 + k0 * 2));
            split8_store(v0, v1, smem, SM_A_HI + off, SM_A_LO + off);
        }
        // load + split W tile: 128 x 64 floats
#pragma unroll
        for (int it = 0; it < 4; it++) {
            int g  = tid + it * 256;
            int r  = g >> 3;
            int k0 = (g & 7) * 8;
            const float* p = W + (size_t)(col0 + r) * K + ch * 64 + k0;
            float4 v0 = *reinterpret_cast<const float4*>(p);
            float4 v1 = *reinterpret_cast<const float4*>(p + 4);
            uint32_t off = SMEM_SWIZZLE_128B((uint32_t)(r * 128 + k0 * 2));
            split8_store(v0, v1, smem, SM_W_HI + off, SM_W_LO + off);
        }
        __syncthreads();

#pragma unroll
        for (int ks = 0; ks < 4; ks++) {
            uint32_t Ah[4][4], Al[4][4], Bh[4][2], Bl[4][2];
#pragma unroll
            for (int fm = 0; fm < 4; fm++) {
                uint32_t loc = (uint32_t)((a_row + fm * 16) * 128 + ks * 32 + a_kb);
                loc = SMEM_SWIZZLE_128B(loc);
                ldm_x4(Ah[fm], sb + SM_A_HI + loc);
                ldm_x4(Al[fm], sb + SM_A_LO + loc);
            }
#pragma unroll
            for (int fn = 0; fn < 4; fn++) {
                uint32_t loc = (uint32_t)((b_row + fn * 8) * 128 + ks * 32 + b_kb);
                loc = SMEM_SWIZZLE_128B(loc);
                ldm_x2(Bh[fn], sb + SM_W_HI + loc);
                ldm_x2(Bl[fn], sb + SM_W_LO + loc);
            }
#pragma unroll
            for (int fm = 0; fm < 4; fm++)
#pragma unroll
                for (int fn = 0; fn < 4; fn++) {
                    float* c = acc[fm][fn];
                    mma_bf16(c, Ah[fm][0], Ah[fm][1], Ah[fm][2], Ah[fm][3], Bh[fn][0], Bh[fn][1]);
                    mma_bf16(c, Ah[fm][0], Ah[fm][1], Ah[fm][2], Ah[fm][3], Bl[fn][0], Bl[fn][1]);
                    mma_bf16(c, Al[fm][0], Al[fm][1], Al[fm][2], Al[fm][3], Bh[fn][0], Bh[fn][1]);
                }
        }
    }

    // epilogue: bias (+ReLU), float2 stores
    const int gid  = lane >> 2;
    const int tid4 = lane & 3;
#pragma unroll
    for (int fn = 0; fn < 4; fn++) {
        const int col = col0 + wn0 + fn * 8 + 2 * tid4;
        const float b0 = bias[col], b1 = bias[col + 1];
#pragma unroll
        for (int fm = 0; fm < 4; fm++) {
            const int rlo = row0 + wm0 + fm * 16 + gid;
            float2 v0, v1;
            v0.x = acc[fm][fn][0] + b0;  v0.y = acc[fm][fn][1] + b1;
            v1.x = acc[fm][fn][2] + b0;  v1.y = acc[fm][fn][3] + b1;
            if (RELU) {
                v0.x = fmaxf(v0.x, 0.f); v0.y = fmaxf(v0.y, 0.f);
                v1.x = fmaxf(v1.x, 0.f); v1.y = fmaxf(v1.y, 0.f);
            }
            *reinterpret_cast<float2*>(C + (size_t)rlo * M + col)       = v0;
            *reinterpret_cast<float2*>(C + (size_t)(rlo + 8) * M + col) = v1;
        }
    }
}

// ---------------------------------------------------------------------------
// GRU gates, k=0 (x == 0 -> gi == b_ih), float4-vectorized.
// ---------------------------------------------------------------------------
__global__ void gates0_kernel(const float* __restrict__ gh,
                              const float* __restrict__ b_ih,
                              const float* __restrict__ h,
                              float* __restrict__ h1)
{
    const int idx = blockIdx.x * blockDim.x + threadIdx.x;  // over NROWS*64
    const int i = idx >> 6;
    const int q = idx & 63;
    const float4* ghr = reinterpret_cast<const float4*>(gh + (size_t)i * H3);
    const float4* bi  = reinterpret_cast<const float4*>(b_ih);
    float4 gr = ghr[q], gz = ghr[64 + q], gn = ghr[128 + q];
    float4 br = bi[q],  bz = bi[64 + q],  bn = bi[128 + q];
    float4 hh = reinterpret_cast<const float4*>(h)[(size_t)i * 64 + q];
    float4 o;
    { float r = sigmoidf_(br.x + gr.x), z = sigmoidf_(bz.x + gz.x);
      float n = tanhf(bn.x + r * gn.x); o.x = (1.f - z) * n + z * hh.x; }
    { float r = sigmoidf_(br.y + gr.y), z = sigmoidf_(bz.y + gz.y);
      float n = tanhf(bn.y + r * gn.y); o.y = (1.f - z) * n + z * hh.y; }
    { float r = sigmoidf_(br.z + gr.z), z = sigmoidf_(bz.z + gz.z);
      float n = tanhf(bn.z + r * gn.z); o.z = (1.f - z) * n + z * hh.z; }
    { float r = sigmoidf_(br.w + gr.w), z = sigmoidf_(bz.w + gz.w);
      float n = tanhf(bn.w + r * gn.w); o.w = (1.f - z) * n + z * hh.w; }
    reinterpret_cast<float4*>(h1)[(size_t)i * 64 + q] = o;
}

// ---------------------------------------------------------------------------
// Comm tensor: c[b,a,:] = (sum_a' h1[b,a',:] - h1[b,a,:]) / NA
// ---------------------------------------------------------------------------
__global__ void comm_kernel(const float* __restrict__ h1, float* __restrict__ c)
{
    const int b = blockIdx.x;
    const int j = threadIdx.x;
    const float* base = h1 + (size_t)b * NA * HD + j;
    float v[NA];
    float s = 0.f;
#pragma unroll
    for (int a = 0; a < NA; a++) { v[a] = base[a * HD]; s += v[a]; }
    float* cb = c + (size_t)b * NA * HD + j;
    const float inv = 1.f / (float)NA;
#pragma unroll
    for (int a = 0; a < NA; a++) cb[a * HD] = (s - v[a]) * inv;
}

// ---------------------------------------------------------------------------
// GRU gates k=1 fused with H->1 decoder. 4 rows / 256-thread block.
// ---------------------------------------------------------------------------
__global__ void gates1_dec_kernel(const float* __restrict__ gi,
                                  const float* __restrict__ gh,
                                  const float* __restrict__ h1,
                                  const float* __restrict__ dec_W,
                                  const float* __restrict__ dec_b,
                                  float* __restrict__ out)
{
    const int tid = threadIdx.x;
    const int i = blockIdx.x * 4 + (tid >> 6);
    const int q = tid & 63;
    const float4* gir = reinterpret_cast<const float4*>(gi + (size_t)i * H3);
    const float4* ghr = reinterpret_cast<const float4*>(gh + (size_t)i * H3);
    float4 ir = gir[q], iz = gir[64 + q], in_ = gir[128 + q];
    float4 hr = ghr[q], hz = ghr[64 + q], hn = ghr[128 + q];
    float4 hp = reinterpret_cast<const float4*>(h1)[(size_t)i * 64 + q];
    float4 dw = reinterpret_cast<const float4*>(dec_W)[q];

    float p = 0.f;
    { float r = sigmoidf_(ir.x + hr.x), z = sigmoidf_(iz.x + hz.x);
      float n = tanhf(in_.x + r * hn.x); p += ((1.f - z) * n + z * hp.x) * dw.x; }
    { float r = sigmoidf_(ir.y + hr.y), z = sigmoidf_(iz.y + hz.y);
      float n = tanhf(in_.y + r * hn.y); p += ((1.f - z) * n + z * hp.y) * dw.y; }
    { float r = sigmoidf_(ir.z + hr.z), z = sigmoidf_(iz.z + hz.z);
      float n = tanhf(in_.z + r * hn.z); p += ((1.f - z) * n + z * hp.z) * dw.z; }
    { float r = sigmoidf_(ir.w + hr.w), z = sigmoidf_(iz.w + hz.w);
      float n = tanhf(in_.w + r * hn.w); p += ((1.f - z) * n + z * hp.w) * dw.w; }
#pragma unroll
    for (int o = 16; o > 0; o >>= 1) p += __shfl_down_sync(0xffffffffu, p, o);
    __shared__ float red[8];
    if ((tid & 31) == 0) red[tid >> 5] = p;
    __syncthreads();
    if (tid < 4) out[blockIdx.x * 4 + tid] = red[2 * tid] + red[2 * tid + 1] + dec_b[0];
}

// ---------------------------------------------------------------------------
// Launch
// ---------------------------------------------------------------------------
extern "C" void kernel_launch(void* const* d_in, const int* in_sizes, int n_in,
                              void* d_out, int out_size)
{
    const float* obs    = (const float*)d_in[0];
    const float* enc_W  = (const float*)d_in[2];
    const float* enc_b  = (const float*)d_in[3];
    const float* fobs_W = (const float*)d_in[4];
    const float* fobs_b = (const float*)d_in[5];
    const float* W_ih   = (const float*)d_in[6];
    const float* b_ih   = (const float*)d_in[7];
    const float* W_hh   = (const float*)d_in[8];
    const float* b_hh   = (const float*)d_in[9];
    const float* dec_W  = (const float*)d_in[10];
    const float* dec_b  = (const float*)d_in[11];
    float* out = (float*)d_out;

    float *e, *h, *h1, *gh, *gi;
    cudaGetSymbolAddress((void**)&e,  g_e);
    cudaGetSymbolAddress((void**)&h,  g_h);
    cudaGetSymbolAddress((void**)&h1, g_h1);
    cudaGetSymbolAddress((void**)&gh, g_gh);
    cudaGetSymbolAddress((void**)&gi, g_gi);

    cudaFuncSetAttribute(mma_gemm<true >, cudaFuncAttributeMaxDynamicSharedMemorySize, SM_TOTAL);
    cudaFuncSetAttribute(mma_gemm<false>, cudaFuncAttributeMaxDynamicSharedMemorySize, SM_TOTAL);

    const dim3 blk(256);
    const int rowBlocks = NROWS / 128;  // 512

    // 1) e = relu(obs @ enc_W^T + enc_b)           K=128, M=256
    mma_gemm<true ><<<dim3(HD / 128, rowBlocks), blk, SM_TOTAL>>>(obs, enc_W, enc_b, e, DIN, HD);
    // 2) h = e @ fobs_W^T + fobs_b                 K=256, M=256
    mma_gemm<false><<<dim3(HD / 128, rowBlocks), blk, SM_TOTAL>>>(e, fobs_W, fobs_b, h, HD, HD);
    // 3) gh = h @ W_hh^T + b_hh                    K=256, M=768
    mma_gemm<false><<<dim3(H3 / 128, rowBlocks), blk, SM_TOTAL>>>(h, W_hh, b_hh, gh, HD, H3);
    // 4) GRU k=0 gates -> h1
    gates0_kernel<<<(NROWS * 64) / 256, 256>>>(gh, b_ih, h, h1);
    // 5) c = masked mean (reuse e)
    comm_kernel<<<NB, HD>>>(h1, e);
    // 6) gi = c @ W_ih^T + b_ih
    mma_gemm<false><<<dim3(H3 / 128, rowBlocks), blk, SM_TOTAL>>>(e, W_ih, b_ih, gi, HD, H3);
    // 7) gh = h1 @ W_hh^T + b_hh
    mma_gemm<false><<<dim3(H3 / 128, rowBlocks), blk, SM_TOTAL>>>(h1, W_hh, b_hh, gh, HD, H3);
    // 8) GRU k=1 gates + decoder -> out
    gates1_dec_kernel<<<NROWS / 4, 256>>>(gi, gh, h1, dec_W, dec_b, out);
}

// round 4
// speedup vs baseline: 2.5592x; 1.7208x over previous
#include <cuda_runtime.h>
#include <cuda_bf16.h>
#include <math.h>
#include <stdint.h>

// Problem constants (B=2048, A=32, D=128, H=256)
#define NB    2048
#define NA    32
#define NROWS (NB * NA)   // 65536
#define DIN   128
#define HD    256
#define H3    768

// ---------------------------------------------------------------------------
// Scratch (__device__ globals; uint4 arrays guarantee 16B alignment for cp.async)
// ---------------------------------------------------------------------------
__device__ float g_h [(size_t)NROWS * HD];
__device__ float g_h1[(size_t)NROWS * HD];
__device__ float g_gh[(size_t)NROWS * H3];
__device__ float g_gi[(size_t)NROWS * H3];

__device__ uint4 g_obs_hi[(size_t)NROWS * DIN / 8];
__device__ uint4 g_obs_lo[(size_t)NROWS * DIN / 8];
__device__ uint4 g_e_hi  [(size_t)NROWS * HD / 8];   // e, later reused as comm c
__device__ uint4 g_e_lo  [(size_t)NROWS * HD / 8];
__device__ uint4 g_hh_hi [(size_t)NROWS * HD / 8];   // h split
__device__ uint4 g_hh_lo [(size_t)NROWS * HD / 8];
__device__ uint4 g_h1_hi [(size_t)NROWS * HD / 8];
__device__ uint4 g_h1_lo [(size_t)NROWS * HD / 8];
__device__ uint4 g_ew_hi [(size_t)HD * DIN / 8];
__device__ uint4 g_ew_lo [(size_t)HD * DIN / 8];
__device__ uint4 g_fw_hi [(size_t)HD * HD / 8];
__device__ uint4 g_fw_lo [(size_t)HD * HD / 8];
__device__ uint4 g_wih_hi[(size_t)H3 * HD / 8];
__device__ uint4 g_wih_lo[(size_t)H3 * HD / 8];
__device__ uint4 g_whh_hi[(size_t)H3 * HD / 8];
__device__ uint4 g_whh_lo[(size_t)H3 * HD / 8];

__device__ __forceinline__ float sigmoidf_(float x) { return 1.0f / (1.0f + expf(-x)); }

__device__ __forceinline__ uint32_t smem_to_u32(const void* p) {
    uint32_t a;
    asm("{ .reg .u64 t; cvta.to.shared.u64 t, %1; cvt.u32.u64 %0, t; }" : "=r"(a) : "l"(p));
    return a;
}

#define SMEM_SWIZZLE_128B(off) ((off) ^ (((off) >> 3) & 0x70))

// ---------------------------------------------------------------------------
// mma / ldmatrix / cp.async primitives (baseline sm_80+ ISA)
// ---------------------------------------------------------------------------
__device__ __forceinline__ void mma_bf16(float* c, uint32_t a0, uint32_t a1, uint32_t a2,
                                         uint32_t a3, uint32_t b0, uint32_t b1) {
    asm volatile(
        "mma.sync.aligned.m16n8k16.row.col.f32.bf16.bf16.f32 "
        "{%0,%1,%2,%3}, {%4,%5,%6,%7}, {%8,%9}, {%0,%1,%2,%3};"
        : "+f"(c[0]), "+f"(c[1]), "+f"(c[2]), "+f"(c[3])
        : "r"(a0), "r"(a1), "r"(a2), "r"(a3), "r"(b0), "r"(b1));
}
__device__ __forceinline__ void ldm_x4(uint32_t* r, uint32_t addr) {
    asm volatile("ldmatrix.sync.aligned.m8n8.x4.shared.b16 {%0,%1,%2,%3}, [%4];"
                 : "=r"(r[0]), "=r"(r[1]), "=r"(r[2]), "=r"(r[3]) : "r"(addr));
}
__device__ __forceinline__ void ldm_x2(uint32_t* r, uint32_t addr) {
    asm volatile("ldmatrix.sync.aligned.m8n8.x2.shared.b16 {%0,%1}, [%2];"
                 : "=r"(r[0]), "=r"(r[1]) : "r"(addr));
}
__device__ __forceinline__ void cp16(uint32_t dst, const void* src) {
    asm volatile("cp.async.cg.shared.global [%0], [%1], 16;" :: "r"(dst), "l"(src));
}
#define CP_COMMIT()  asm volatile("cp.async.commit_group;")
#define CP_WAIT(n)   asm volatile("cp.async.wait_group %0;" :: "n"(n))

// hi/lo bf16 split helpers
__device__ __forceinline__ void split2(float a, float b, uint32_t& hi, uint32_t& lo) {
    __nv_bfloat16 ha = __float2bfloat16_rn(a);
    __nv_bfloat16 hb = __float2bfloat16_rn(b);
    float ra = a - __bfloat162float(ha);
    float rb = b - __bfloat162float(hb);
    __nv_bfloat16 la = __float2bfloat16_rn(ra);
    __nv_bfloat16 lb = __float2bfloat16_rn(rb);
    hi = (uint32_t)__bfloat16_as_ushort(ha) | ((uint32_t)__bfloat16_as_ushort(hb) << 16);
    lo = (uint32_t)__bfloat16_as_ushort(la) | ((uint32_t)__bfloat16_as_ushort(lb) << 16);
}

// ---------------------------------------------------------------------------
// fp32 -> bf16 hi/lo conversion (weights + obs), float4 per thread
// ---------------------------------------------------------------------------
__global__ void convert_split(const float4* __restrict__ src,
                              uint2* __restrict__ hi, uint2* __restrict__ lo, int n4)
{
    const int i = blockIdx.x * blockDim.x + threadIdx.x;
    if (i >= n4) return;
    float4 v = src[i];
    uint2 H, L;
    split2(v.x, v.y, H.x, L.x);
    split2(v.z, v.w, H.y, L.y);
    hi[i] = H;
    lo[i] = L;
}

// ---------------------------------------------------------------------------
// bf16-split GEMM, cp.async double-buffered:
//   C[N,M] = A[N,K] @ W[M,K]^T + bias  (A, W pre-split into hi/lo bf16)
// CTA tile 128x128, KC=64, 2 stages (128KB smem), 8 warps (2m x 4n).
// Epilogue: optional ReLU, optional fp32 C, optional bf16 hi/lo C.
// ---------------------------------------------------------------------------
#define ST_AH 0
#define ST_AL 16384
#define ST_WH 32768
#define ST_WL 49152
#define ST_SZ 65536
#define SM_TOTAL (2 * ST_SZ)

template <bool RELU, bool WF32, bool WSPLIT>
__global__ __launch_bounds__(256, 1)
void mma_gemm2(const __nv_bfloat16* __restrict__ Ahg, const __nv_bfloat16* __restrict__ Alg,
               const __nv_bfloat16* __restrict__ Whg, const __nv_bfloat16* __restrict__ Wlg,
               const float* __restrict__ bias, float* __restrict__ C,
               __nv_bfloat16* __restrict__ Ch, __nv_bfloat16* __restrict__ Cl,
               int K, int M)
{
    extern __shared__ char smem[];
    const uint32_t sb = smem_to_u32(smem);
    const int tid  = threadIdx.x;
    const int wid  = tid >> 5;
    const int lane = tid & 31;
    const int row0 = blockIdx.y * 128;
    const int col0 = blockIdx.x * 128;
    const int wm0  = (wid >> 2) * 64;
    const int wn0  = (wid & 3) * 32;

    const int a_row = wm0 + (lane & 15);
    const int a_kb  = ((lane >> 4) & 1) * 16;
    const int b_row = wn0 + (lane & 7);
    const int b_kb  = ((lane >> 3) & 1) * 16;

    // per-thread tile-load mapping (4 x 16B per array per stage)
    uint32_t sw[4];
    const __nv_bfloat16 *pA[4], *pAl[4], *pW[4], *pWl[4];
#pragma unroll
    for (int it = 0; it < 4; it++) {
        int g = tid + it * 256;
        int r = g >> 3, k0 = (g & 7) * 8;
        sw[it]  = SMEM_SWIZZLE_128B((uint32_t)(r * 128 + k0 * 2));
        pA[it]  = Ahg + (size_t)(row0 + r) * K + k0;
        pAl[it] = Alg + (size_t)(row0 + r) * K + k0;
        pW[it]  = Whg + (size_t)(col0 + r) * K + k0;
        pWl[it] = Wlg + (size_t)(col0 + r) * K + k0;
    }

    float acc[4][4][4];
#pragma unroll
    for (int i = 0; i < 4; i++)
#pragma unroll
        for (int j = 0; j < 4; j++)
#pragma unroll
            for (int q = 0; q < 4; q++) acc[i][j][q] = 0.f;

    const int nch = K >> 6;

    // prologue: prefetch chunk 0 into stage 0
#pragma unroll
    for (int it = 0; it < 4; it++) {
        cp16(sb + ST_AH + sw[it], pA[it]);
        cp16(sb + ST_AL + sw[it], pAl[it]);
        cp16(sb + ST_WH + sw[it], pW[it]);
        cp16(sb + ST_WL + sw[it], pWl[it]);
    }
    CP_COMMIT();

    for (int ch = 0; ch < nch; ch++) {
        const uint32_t sbase = sb + (uint32_t)(ch & 1) * ST_SZ;
        if (ch + 1 < nch) {
            const uint32_t nbase = sb + (uint32_t)((ch + 1) & 1) * ST_SZ;
            const int koff = (ch + 1) * 64;
#pragma unroll
            for (int it = 0; it < 4; it++) {
                cp16(nbase + ST_AH + sw[it], pA[it]  + koff);
                cp16(nbase + ST_AL + sw[it], pAl[it] + koff);
                cp16(nbase + ST_WH + sw[it], pW[it]  + koff);
                cp16(nbase + ST_WL + sw[it], pWl[it] + koff);
            }
            CP_COMMIT();
            CP_WAIT(1);
        } else {
            CP_WAIT(0);
        }
        __syncthreads();

#pragma unroll
        for (int ks = 0; ks < 4; ks++) {
            uint32_t Ah[4][4], Al[4][4], Bh[4][2], Bl[4][2];
#pragma unroll
            for (int fm = 0; fm < 4; fm++) {
                uint32_t loc = SMEM_SWIZZLE_128B((uint32_t)((a_row + fm * 16) * 128 + ks * 32 + a_kb));
                ldm_x4(Ah[fm], sbase + ST_AH + loc);
                ldm_x4(Al[fm], sbase + ST_AL + loc);
            }
#pragma unroll
            for (int fn = 0; fn < 4; fn++) {
                uint32_t loc = SMEM_SWIZZLE_128B((uint32_t)((b_row + fn * 8) * 128 + ks * 32 + b_kb));
                ldm_x2(Bh[fn], sbase + ST_WH + loc);
                ldm_x2(Bl[fn], sbase + ST_WL + loc);
            }
#pragma unroll
            for (int fm = 0; fm < 4; fm++)
#pragma unroll
                for (int fn = 0; fn < 4; fn++) {
                    float* c = acc[fm][fn];
                    mma_bf16(c, Ah[fm][0], Ah[fm][1], Ah[fm][2], Ah[fm][3], Bh[fn][0], Bh[fn][1]);
                    mma_bf16(c, Ah[fm][0], Ah[fm][1], Ah[fm][2], Ah[fm][3], Bl[fn][0], Bl[fn][1]);
                    mma_bf16(c, Al[fm][0], Al[fm][1], Al[fm][2], Al[fm][3], Bh[fn][0], Bh[fn][1]);
                }
        }
        __syncthreads();
    }

    // epilogue
    const int gid  = lane >> 2;
    const int tid4 = lane & 3;
#pragma unroll
    for (int fn = 0; fn < 4; fn++) {
        const int col = col0 + wn0 + fn * 8 + 2 * tid4;
        const float b0 = bias[col], b1 = bias[col + 1];
#pragma unroll
        for (int fm = 0; fm < 4; fm++) {
            const int rlo = row0 + wm0 + fm * 16 + gid;
            float2 v0, v1;
            v0.x = acc[fm][fn][0] + b0;  v0.y = acc[fm][fn][1] + b1;
            v1.x = acc[fm][fn][2] + b0;  v1.y = acc[fm][fn][3] + b1;
            if (RELU) {
                v0.x = fmaxf(v0.x, 0.f); v0.y = fmaxf(v0.y, 0.f);
                v1.x = fmaxf(v1.x, 0.f); v1.y = fmaxf(v1.y, 0.f);
            }
            if (WF32) {
                *reinterpret_cast<float2*>(C + (size_t)rlo * M + col)       = v0;
                *reinterpret_cast<float2*>(C + (size_t)(rlo + 8) * M + col) = v1;
            }
            if (WSPLIT) {
                uint32_t h0, l0, h1, l1;
                split2(v0.x, v0.y, h0, l0);
                split2(v1.x, v1.y, h1, l1);
                *reinterpret_cast<uint32_t*>(Ch + (size_t)rlo * M + col)       = h0;
                *reinterpret_cast<uint32_t*>(Cl + (size_t)rlo * M + col)       = l0;
                *reinterpret_cast<uint32_t*>(Ch + (size_t)(rlo + 8) * M + col) = h1;
                *reinterpret_cast<uint32_t*>(Cl + (size_t)(rlo + 8) * M + col) = l1;
            }
        }
    }
}

// ---------------------------------------------------------------------------
// GRU gates k=0 (x==0 -> gi == b_ih): writes h1 fp32 AND h1 hi/lo bf16.
// ---------------------------------------------------------------------------
__global__ void gates0_kernel(const float* __restrict__ gh,
                              const float* __restrict__ b_ih,
                              const float* __restrict__ h,
                              float* __restrict__ h1,
                              uint2* __restrict__ h1_hi, uint2* __restrict__ h1_lo)
{
    const int idx = blockIdx.x * blockDim.x + threadIdx.x;  // over NROWS*64
    const int i = idx >> 6;
    const int q = idx & 63;
    const float4* ghr = reinterpret_cast<const float4*>(gh + (size_t)i * H3);
    const float4* bi  = reinterpret_cast<const float4*>(b_ih);
    float4 gr = ghr[q], gz = ghr[64 + q], gn = ghr[128 + q];
    float4 br = bi[q],  bz = bi[64 + q],  bn = bi[128 + q];
    float4 hh = reinterpret_cast<const float4*>(h)[(size_t)i * 64 + q];
    float4 o;
    { float r = sigmoidf_(br.x + gr.x), z = sigmoidf_(bz.x + gz.x);
      float n = tanhf(bn.x + r * gn.x); o.x = (1.f - z) * n + z * hh.x; }
    { float r = sigmoidf_(br.y + gr.y), z = sigmoidf_(bz.y + gz.y);
      float n = tanhf(bn.y + r * gn.y); o.y = (1.f - z) * n + z * hh.y; }
    { float r = sigmoidf_(br.z + gr.z), z = sigmoidf_(bz.z + gz.z);
      float n = tanhf(bn.z + r * gn.z); o.z = (1.f - z) * n + z * hh.z; }
    { float r = sigmoidf_(br.w + gr.w), z = sigmoidf_(bz.w + gz.w);
      float n = tanhf(bn.w + r * gn.w); o.w = (1.f - z) * n + z * hh.w; }
    reinterpret_cast<float4*>(h1)[(size_t)i * 64 + q] = o;
    uint2 H, L;
    split2(o.x, o.y, H.x, L.x);
    split2(o.z, o.w, H.y, L.y);
    h1_hi[(size_t)i * 64 + q] = H;
    h1_lo[(size_t)i * 64 + q] = L;
}

// ---------------------------------------------------------------------------
// Comm: c[b,a,:] = (sum_a' h1[b,a',:] - h1[b,a,:]) / NA, written as bf16 hi/lo
// ---------------------------------------------------------------------------
__global__ void comm_kernel(const float* __restrict__ h1,
                            __nv_bfloat16* __restrict__ c_hi,
                            __nv_bfloat16* __restrict__ c_lo)
{
    const int b = blockIdx.x;
    const int j = threadIdx.x;
    const float* base = h1 + (size_t)b * NA * HD + j;
    float v[NA];
    float s = 0.f;
#pragma unroll
    for (int a = 0; a < NA; a++) { v[a] = base[a * HD]; s += v[a]; }
    const float inv = 1.f / (float)NA;
    const size_t off = (size_t)b * NA * HD + j;
#pragma unroll
    for (int a = 0; a < NA; a++) {
        float val = (s - v[a]) * inv;
        __nv_bfloat16 hv = __float2bfloat16_rn(val);
        c_hi[off + a * HD] = hv;
        c_lo[off + a * HD] = __float2bfloat16_rn(val - __bfloat162float(hv));
    }
}

// ---------------------------------------------------------------------------
// GRU gates k=1 fused with H->1 decoder. 4 rows / 256-thread block.
// ---------------------------------------------------------------------------
__global__ void gates1_dec_kernel(const float* __restrict__ gi,
                                  const float* __restrict__ gh,
                                  const float* __restrict__ h1,
                                  const float* __restrict__ dec_W,
                                  const float* __restrict__ dec_b,
                                  float* __restrict__ out)
{
    const int tid = threadIdx.x;
    const int i = blockIdx.x * 4 + (tid >> 6);
    const int q = tid & 63;
    const float4* gir = reinterpret_cast<const float4*>(gi + (size_t)i * H3);
    const float4* ghr = reinterpret_cast<const float4*>(gh + (size_t)i * H3);
    float4 ir = gir[q], iz = gir[64 + q], in_ = gir[128 + q];
    float4 hr = ghr[q], hz = ghr[64 + q], hn = ghr[128 + q];
    float4 hp = reinterpret_cast<const float4*>(h1)[(size_t)i * 64 + q];
    float4 dw = reinterpret_cast<const float4*>(dec_W)[q];

    float p = 0.f;
    { float r = sigmoidf_(ir.x + hr.x), z = sigmoidf_(iz.x + hz.x);
      float n = tanhf(in_.x + r * hn.x); p += ((1.f - z) * n + z * hp.x) * dw.x; }
    { float r = sigmoidf_(ir.y + hr.y), z = sigmoidf_(iz.y + hz.y);
      float n = tanhf(in_.y + r * hn.y); p += ((1.f - z) * n + z * hp.y) * dw.y; }
    { float r = sigmoidf_(ir.z + hr.z), z = sigmoidf_(iz.z + hz.z);
      float n = tanhf(in_.z + r * hn.z); p += ((1.f - z) * n + z * hp.z) * dw.z; }
    { float r = sigmoidf_(ir.w + hr.w), z = sigmoidf_(iz.w + hz.w);
      float n = tanhf(in_.w + r * hn.w); p += ((1.f - z) * n + z * hp.w) * dw.w; }
#pragma unroll
    for (int o = 16; o > 0; o >>= 1) p += __shfl_down_sync(0xffffffffu, p, o);
    __shared__ float red[8];
    if ((tid & 31) == 0) red[tid >> 5] = p;
    __syncthreads();
    if (tid < 4) out[blockIdx.x * 4 + tid] = red[2 * tid] + red[2 * tid + 1] + dec_b[0];
}

// ---------------------------------------------------------------------------
// Launch
// ---------------------------------------------------------------------------
extern "C" void kernel_launch(void* const* d_in, const int* in_sizes, int n_in,
                              void* d_out, int out_size)
{
    const float* obs    = (const float*)d_in[0];
    const float* enc_W  = (const float*)d_in[2];
    const float* enc_b  = (const float*)d_in[3];
    const float* fobs_W = (const float*)d_in[4];
    const float* fobs_b = (const float*)d_in[5];
    const float* W_ih   = (const float*)d_in[6];
    const float* b_ih   = (const float*)d_in[7];
    const float* W_hh   = (const float*)d_in[8];
    const float* b_hh   = (const float*)d_in[9];
    const float* dec_W  = (const float*)d_in[10];
    const float* dec_b  = (const float*)d_in[11];
    float* out = (float*)d_out;

    float *h, *h1, *gh, *gi;
    cudaGetSymbolAddress((void**)&h,  g_h);
    cudaGetSymbolAddress((void**)&h1, g_h1);
    cudaGetSymbolAddress((void**)&gh, g_gh);
    cudaGetSymbolAddress((void**)&gi, g_gi);

    void *obs_hi, *obs_lo, *e_hi, *e_lo, *hh_hi, *hh_lo, *h1_hi, *h1_lo;
    void *ew_hi, *ew_lo, *fw_hi, *fw_lo, *wih_hi, *wih_lo, *whh_hi, *whh_lo;
    cudaGetSymbolAddress(&obs_hi, g_obs_hi);  cudaGetSymbolAddress(&obs_lo, g_obs_lo);
    cudaGetSymbolAddress(&e_hi,  g_e_hi);     cudaGetSymbolAddress(&e_lo,  g_e_lo);
    cudaGetSymbolAddress(&hh_hi, g_hh_hi);    cudaGetSymbolAddress(&hh_lo, g_hh_lo);
    cudaGetSymbolAddress(&h1_hi, g_h1_hi);    cudaGetSymbolAddress(&h1_lo, g_h1_lo);
    cudaGetSymbolAddress(&ew_hi, g_ew_hi);    cudaGetSymbolAddress(&ew_lo, g_ew_lo);
    cudaGetSymbolAddress(&fw_hi, g_fw_hi);    cudaGetSymbolAddress(&fw_lo, g_fw_lo);
    cudaGetSymbolAddress(&wih_hi, g_wih_hi);  cudaGetSymbolAddress(&wih_lo, g_wih_lo);
    cudaGetSymbolAddress(&whh_hi, g_whh_hi);  cudaGetSymbolAddress(&whh_lo, g_whh_lo);

    cudaFuncSetAttribute(mma_gemm2<true , false, true >, cudaFuncAttributeMaxDynamicSharedMemorySize, SM_TOTAL);
    cudaFuncSetAttribute(mma_gemm2<false, true , true >, cudaFuncAttributeMaxDynamicSharedMemorySize, SM_TOTAL);
    cudaFuncSetAttribute(mma_gemm2<false, true , false>, cudaFuncAttributeMaxDynamicSharedMemorySize, SM_TOTAL);

    typedef const __nv_bfloat16* bfp;
    typedef __nv_bfloat16* bfpm;

    // 0) pre-split obs + weights to bf16 hi/lo
    convert_split<<<(NROWS * DIN / 4 + 255) / 256, 256>>>((const float4*)obs, (uint2*)obs_hi, (uint2*)obs_lo, NROWS * DIN / 4);
    convert_split<<<(HD * DIN / 4 + 255) / 256, 256>>>((const float4*)enc_W,  (uint2*)ew_hi,  (uint2*)ew_lo,  HD * DIN / 4);
    convert_split<<<(HD * HD  / 4 + 255) / 256, 256>>>((const float4*)fobs_W, (uint2*)fw_hi,  (uint2*)fw_lo,  HD * HD / 4);
    convert_split<<<(H3 * HD  / 4 + 255) / 256, 256>>>((const float4*)W_ih,   (uint2*)wih_hi, (uint2*)wih_lo, H3 * HD / 4);
    convert_split<<<(H3 * HD  / 4 + 255) / 256, 256>>>((const float4*)W_hh,   (uint2*)whh_hi, (uint2*)whh_lo, H3 * HD / 4);

    const dim3 blk(256);
    const int rowBlocks = NROWS / 128;  // 512

    // 1) e = relu(obs @ enc_W^T + enc_b) -> e_hi/e_lo       K=128, M=256
    mma_gemm2<true, false, true><<<dim3(2, rowBlocks), blk, SM_TOTAL>>>(
        (bfp)obs_hi, (bfp)obs_lo, (bfp)ew_hi, (bfp)ew_lo, enc_b,
        nullptr, (bfpm)e_hi, (bfpm)e_lo, DIN, HD);
    // 2) h = e @ fobs_W^T + fobs_b -> h fp32 + h_hi/h_lo    K=256, M=256
    mma_gemm2<false, true, true><<<dim3(2, rowBlocks), blk, SM_TOTAL>>>(
        (bfp)e_hi, (bfp)e_lo, (bfp)fw_hi, (bfp)fw_lo, fobs_b,
        h, (bfpm)hh_hi, (bfpm)hh_lo, HD, HD);
    // 3) gh = h @ W_hh^T + b_hh                             K=256, M=768
    mma_gemm2<false, true, false><<<dim3(6, rowBlocks), blk, SM_TOTAL>>>(
        (bfp)hh_hi, (bfp)hh_lo, (bfp)whh_hi, (bfp)whh_lo, b_hh,
        gh, nullptr, nullptr, HD, H3);
    // 4) GRU k=0 gates -> h1 (fp32 + hi/lo)
    gates0_kernel<<<(NROWS * 64) / 256, 256>>>(gh, b_ih, h, h1, (uint2*)h1_hi, (uint2*)h1_lo);
    // 5) c = masked mean -> c_hi/c_lo (reuse e buffers)
    comm_kernel<<<NB, HD>>>(h1, (bfpm)e_hi, (bfpm)e_lo);
    // 6) gi = c @ W_ih^T + b_ih
    mma_gemm2<false, true, false><<<dim3(6, rowBlocks), blk, SM_TOTAL>>>(
        (bfp)e_hi, (bfp)e_lo, (bfp)wih_hi, (bfp)wih_lo, b_ih,
        gi, nullptr, nullptr, HD, H3);
    // 7) gh = h1 @ W_hh^T + b_hh
    mma_gemm2<false, true, false><<<dim3(6, rowBlocks), blk, SM_TOTAL>>>(
        (bfp)h1_hi, (bfp)h1_lo, (bfp)whh_hi, (bfp)whh_lo, b_hh,
        gh, nullptr, nullptr, HD, H3);
    // 8) GRU k=1 gates + decoder -> out
    gates1_dec_kernel<<<NROWS / 4, 256>>>(gi, gh, h1, dec_W, dec_b, out);
}